// round 4
// baseline (speedup 1.0000x reference)
#include <cuda_runtime.h>

#define S_LEN 4096
#define NB    4
#define DIN   512
#define DOUT  64

// Scratch for projected Q, K, V: [B*S, 64] each (4 MB each). __device__ globals
// are the sanctioned scratch mechanism (no cudaMalloc allowed).
__device__ float g_Q[NB * S_LEN * DOUT];
__device__ float g_K[NB * S_LEN * DOUT];
__device__ float g_V[NB * S_LEN * DOUT];

#define NEG_INF (-1e30f)

// ---------------------------------------------------------------------------
// Projection: Y = X @ W for (Q,K,V).  X: [16384, 512], W: [512, 64].
// Block = 256 threads computes a 64x64 output tile (full output width),
// K staged in chunks of 32. Per-thread 4x4 register tile.
// ---------------------------------------------------------------------------
__global__ __launch_bounds__(256) void proj_kernel(
    const float* __restrict__ Xk, const float* __restrict__ Xv,
    const float* __restrict__ Xq, const float* __restrict__ Wq,
    const float* __restrict__ Wk, const float* __restrict__ Wv)
{
    __shared__ float Xs[32][68];   // [k][row]  (transposed; pad vs store conflicts)
    __shared__ float Ws[32][68];   // [k][e]

    const float* __restrict__ X;
    const float* __restrict__ W;
    float* __restrict__ Y;
    if (blockIdx.y == 0)      { X = Xq; W = Wq; Y = g_Q; }
    else if (blockIdx.y == 1) { X = Xk; W = Wk; Y = g_K; }
    else                      { X = Xv; W = Wv; Y = g_V; }

    const int tid  = threadIdx.x;
    const int tr   = tid >> 4;       // 0..15  -> rows tr*4..tr*4+3
    const int tc   = tid & 15;       // 0..15  -> cols tc*4..tc*4+3
    const int row0 = blockIdx.x * 64;

    float acc[4][4];
#pragma unroll
    for (int i = 0; i < 4; ++i)
#pragma unroll
        for (int j = 0; j < 4; ++j) acc[i][j] = 0.0f;

#pragma unroll 1
    for (int k0 = 0; k0 < DIN; k0 += 32) {
        // Load X tile (64 rows x 32 k), store transposed: Xs[k][row]
#pragma unroll
        for (int it = 0; it < 2; ++it) {
            int idx = tid + it * 256;            // 0..511
            int r   = idx >> 3;                  // 0..63
            int kk  = (idx & 7) << 2;            // 0,4,...,28
            float4 v = *(const float4*)(X + (size_t)(row0 + r) * DIN + k0 + kk);
            Xs[kk + 0][r] = v.x;
            Xs[kk + 1][r] = v.y;
            Xs[kk + 2][r] = v.z;
            Xs[kk + 3][r] = v.w;
        }
        // Load W tile (32 k x 64 e), natural layout
#pragma unroll
        for (int it = 0; it < 2; ++it) {
            int idx = tid + it * 256;
            int kk  = idx >> 4;                  // 0..31
            int e   = (idx & 15) << 2;           // 0..60
            *(float4*)(&Ws[kk][e]) =
                *(const float4*)(W + (size_t)(k0 + kk) * DOUT + e);
        }
        __syncthreads();

#pragma unroll
        for (int k = 0; k < 32; ++k) {
            float4 a4 = *(const float4*)(&Xs[k][tr << 2]);
            float4 b4 = *(const float4*)(&Ws[k][tc << 2]);
            float ar[4] = {a4.x, a4.y, a4.z, a4.w};
            float br[4] = {b4.x, b4.y, b4.z, b4.w};
#pragma unroll
            for (int i = 0; i < 4; ++i)
#pragma unroll
                for (int j = 0; j < 4; ++j)
                    acc[i][j] = fmaf(ar[i], br[j], acc[i][j]);
        }
        __syncthreads();
    }

#pragma unroll
    for (int i = 0; i < 4; ++i) {
        float4 o = make_float4(acc[i][0], acc[i][1], acc[i][2], acc[i][3]);
        *(float4*)(Y + (size_t)(row0 + (tr << 2) + i) * DOUT + (tc << 2)) = o;
    }
}

// ---------------------------------------------------------------------------
// Flash attention, fp32, causal. Block = 256 threads handles TWO 64-row query
// tiles (z and 63-z) so all 128 blocks do exactly 65 kv-tile iterations.
// Per kv tile: S = Q K^T * 0.125 (64x64x64), online softmax, O += P V.
// smem: Qs [d][r], KP aliased (K as [d][c] then P as [c][r]), Vs [c][e].
// Exactly 48 KB static shared.
// ---------------------------------------------------------------------------
__global__ __launch_bounds__(256) void attn_kernel(float* __restrict__ out)
{
    __shared__ float Qs[64 * 64];   // [d][r]
    __shared__ float KP[64 * 64];   // phase 1: K [d][c]; phase 2: P [c][r]
    __shared__ float Vs[64 * 64];   // [c][e]

    const int b   = blockIdx.y;
    const int tid = threadIdx.x;
    const int tr  = tid >> 4;
    const int tc  = tid & 15;
    const int r0  = tr << 2;
    const int c0  = tc << 2;

    const float* __restrict__ Qb = g_Q + (size_t)b * S_LEN * DOUT;
    const float* __restrict__ Kb = g_K + (size_t)b * S_LEN * DOUT;
    const float* __restrict__ Vb = g_V + (size_t)b * S_LEN * DOUT;
    float* __restrict__ Ob = out + (size_t)b * S_LEN * DOUT;

#pragma unroll 1
    for (int half = 0; half < 2; ++half) {
        const int qt    = (half == 0) ? (int)blockIdx.x : (63 - (int)blockIdx.x);
        const int qbase = qt << 6;

        __syncthreads();   // previous half's smem reads complete
        // Load Q tile transposed: Qs[d][r] = Q[qbase+r][d]
#pragma unroll
        for (int it = 0; it < 4; ++it) {
            int idx = tid + it * 256;            // 0..1023
            int r   = idx >> 4;                  // 0..63
            int d0  = (idx & 15) << 2;           // 0..60
            float4 v = *(const float4*)(Qb + (size_t)(qbase + r) * DOUT + d0);
            Qs[(d0 + 0) * 64 + r] = v.x;
            Qs[(d0 + 1) * 64 + r] = v.y;
            Qs[(d0 + 2) * 64 + r] = v.z;
            Qs[(d0 + 3) * 64 + r] = v.w;
        }

        float m[4], l[4], acc[4][4];
#pragma unroll
        for (int i = 0; i < 4; ++i) {
            m[i] = NEG_INF;
            l[i] = 0.0f;
#pragma unroll
            for (int j = 0; j < 4; ++j) acc[i][j] = 0.0f;
        }

#pragma unroll 1
        for (int jt = 0; jt <= qt; ++jt) {
            const int kbase = jt << 6;
            __syncthreads();   // prior PV reads of KP/Vs done; Qs stores done (1st iter)
            // K transposed into KP [d][c]; V natural into Vs [c][e]
#pragma unroll
            for (int it = 0; it < 4; ++it) {
                int idx = tid + it * 256;
                int c   = idx >> 4;
                int d0  = (idx & 15) << 2;
                float4 kv = *(const float4*)(Kb + (size_t)(kbase + c) * DOUT + d0);
                KP[(d0 + 0) * 64 + c] = kv.x;
                KP[(d0 + 1) * 64 + c] = kv.y;
                KP[(d0 + 2) * 64 + c] = kv.z;
                KP[(d0 + 3) * 64 + c] = kv.w;
                *(float4*)(&Vs[c * 64 + d0]) =
                    *(const float4*)(Vb + (size_t)(kbase + c) * DOUT + d0);
            }
            __syncthreads();

            // ---- S = Q K^T ----
            float s[4][4];
#pragma unroll
            for (int i = 0; i < 4; ++i)
#pragma unroll
                for (int j = 0; j < 4; ++j) s[i][j] = 0.0f;

#pragma unroll 16
            for (int d = 0; d < 64; ++d) {
                float4 a4 = *(const float4*)(&Qs[d * 64 + r0]);
                float4 b4 = *(const float4*)(&KP[d * 64 + c0]);
                float ar[4] = {a4.x, a4.y, a4.z, a4.w};
                float br[4] = {b4.x, b4.y, b4.z, b4.w};
#pragma unroll
                for (int i = 0; i < 4; ++i)
#pragma unroll
                    for (int j = 0; j < 4; ++j)
                        s[i][j] = fmaf(ar[i], br[j], s[i][j]);
            }

            // scale + causal mask (only diagonal tile needs masking)
            if (jt == qt) {
#pragma unroll
                for (int i = 0; i < 4; ++i)
#pragma unroll
                    for (int j = 0; j < 4; ++j)
                        s[i][j] = (c0 + j <= r0 + i) ? s[i][j] * 0.125f : NEG_INF;
            } else {
#pragma unroll
                for (int i = 0; i < 4; ++i)
#pragma unroll
                    for (int j = 0; j < 4; ++j)
                        s[i][j] *= 0.125f;
            }

            __syncthreads();   // everyone done reading K before P overwrites KP

            // ---- online softmax + write P [c][r] ----
#pragma unroll
            for (int i = 0; i < 4; ++i) {
                float tm = fmaxf(fmaxf(s[i][0], s[i][1]), fmaxf(s[i][2], s[i][3]));
                tm = fmaxf(tm, __shfl_xor_sync(0xffffffffu, tm, 1));
                tm = fmaxf(tm, __shfl_xor_sync(0xffffffffu, tm, 2));
                tm = fmaxf(tm, __shfl_xor_sync(0xffffffffu, tm, 4));
                tm = fmaxf(tm, __shfl_xor_sync(0xffffffffu, tm, 8));
                float mn   = fmaxf(m[i], tm);
                float corr = __expf(m[i] - mn);
                float p0 = __expf(s[i][0] - mn);
                float p1 = __expf(s[i][1] - mn);
                float p2 = __expf(s[i][2] - mn);
                float p3 = __expf(s[i][3] - mn);
                float ps = (p0 + p1) + (p2 + p3);
                ps += __shfl_xor_sync(0xffffffffu, ps, 1);
                ps += __shfl_xor_sync(0xffffffffu, ps, 2);
                ps += __shfl_xor_sync(0xffffffffu, ps, 4);
                ps += __shfl_xor_sync(0xffffffffu, ps, 8);
                l[i] = l[i] * corr + ps;
                m[i] = mn;
                acc[i][0] *= corr;
                acc[i][1] *= corr;
                acc[i][2] *= corr;
                acc[i][3] *= corr;
                KP[(c0 + 0) * 64 + r0 + i] = p0;
                KP[(c0 + 1) * 64 + r0 + i] = p1;
                KP[(c0 + 2) * 64 + r0 + i] = p2;
                KP[(c0 + 3) * 64 + r0 + i] = p3;
            }
            __syncthreads();

            // ---- O += P V ----
#pragma unroll 16
            for (int c = 0; c < 64; ++c) {
                float4 a4 = *(const float4*)(&KP[c * 64 + r0]);
                float4 v4 = *(const float4*)(&Vs[c * 64 + c0]);
                float ar[4] = {a4.x, a4.y, a4.z, a4.w};
                float vr[4] = {v4.x, v4.y, v4.z, v4.w};
#pragma unroll
                for (int i = 0; i < 4; ++i)
#pragma unroll
                    for (int j = 0; j < 4; ++j)
                        acc[i][j] = fmaf(ar[i], vr[j], acc[i][j]);
            }
        }

        // ---- finalize: Z = acc / l ----
#pragma unroll
        for (int i = 0; i < 4; ++i) {
            float inv = __fdividef(1.0f, l[i]);
            float4 o = make_float4(acc[i][0] * inv, acc[i][1] * inv,
                                   acc[i][2] * inv, acc[i][3] * inv);
            *(float4*)(Ob + (size_t)(qbase + r0 + i) * DOUT + c0) = o;
        }
    }
}

extern "C" void kernel_launch(void* const* d_in, const int* in_sizes, int n_in,
                              void* d_out, int out_size)
{
    (void)in_sizes; (void)n_in; (void)out_size;
    const float* key_in   = (const float*)d_in[0];
    const float* value_in = (const float*)d_in[1];
    const float* query_in = (const float*)d_in[2];
    const float* Wq       = (const float*)d_in[3];
    const float* Wk       = (const float*)d_in[4];
    const float* Wv       = (const float*)d_in[5];
    float* out = (float*)d_out;

    dim3 pgrid(NB * S_LEN / 64, 3);   // (256, 3)
    proj_kernel<<<pgrid, 256>>>(key_in, value_in, query_in, Wq, Wk, Wv);

    dim3 agrid((S_LEN / 64) / 2, NB); // (32, 4): paired q-tiles, uniform 65 iters/block
    attn_kernel<<<agrid, 256>>>(out);
}